// round 2
// baseline (speedup 1.0000x reference)
#include <cuda_runtime.h>
#include <cuda_bf16.h>
#include <math.h>

// ---------------- problem constants ----------------
#define B_   2
#define C_   128
#define H_   48
#define W_   48
#define LL   (H_*W_)      // 2304
#define DD   256
#define NN   16
#define RR   8
#define BL_  (B_*LL)      // 4608

// ---------------- scratch (device globals; no allocs allowed) ----------------
// offsets in floats
#define OFF_XN    ((size_t)0)          // [BL_,128]
#define OFF_XZ    ((size_t)589824)     // [BL_,512]  (xm cols 0..255, z cols 256..511)
#define OFF_XS    ((size_t)2949120)    // [B,4,L,D]
#define OFF_XDBL  ((size_t)7667712)    // [B,4,L,40]
#define OFF_DTS   ((size_t)8404992)    // [B,4,L,D]
#define OFF_YS    ((size_t)13123584)   // [B,4,L,D]
#define OFF_YG    ((size_t)17842176)   // [BL_,D]
#define OFF_XO    ((size_t)19021824)   // [BL_,C]
#define OFF_AO    ((size_t)19611648)   // [BL_,C]
#define OFF_P     ((size_t)20201472)   // [BL_,64]
#define OFF_CH    ((size_t)20496384)   // [BL_,64]
#define SCRATCH_TOTAL 20791296

__device__ float g_scratch[SCRATCH_TOTAL];

// ---------------- LayerNorm over C=128 (channels-last output) ----------------
__global__ void ln_in_kernel(const float* __restrict__ x, const float* __restrict__ g,
                             const float* __restrict__ bt, float* __restrict__ xn)
{
    int row  = blockIdx.x * 8 + (threadIdx.x >> 5);   // (b,hw) row, 4608 total
    int lane = threadIdx.x & 31;
    int b = row / LL, hw = row % LL;
    float v[4];
#pragma unroll
    for (int i = 0; i < 4; i++)
        v[i] = x[((size_t)b * C_ + (lane + 32*i)) * LL + hw];
    float s = v[0] + v[1] + v[2] + v[3];
#pragma unroll
    for (int o = 16; o; o >>= 1) s += __shfl_xor_sync(~0u, s, o);
    float mu = s * (1.f / C_);
    float q = 0.f;
#pragma unroll
    for (int i = 0; i < 4; i++) { float d = v[i] - mu; q += d * d; }
#pragma unroll
    for (int o = 16; o; o >>= 1) q += __shfl_xor_sync(~0u, q, o);
    float inv = rsqrtf(q * (1.f / C_) + 1e-6f);
#pragma unroll
    for (int i = 0; i < 4; i++) {
        int c = lane + 32*i;
        xn[(size_t)row * C_ + c] = (v[i] - mu) * inv * g[c] + bt[c];
    }
}

// ---------------- generic GEMM:  C[M,N] = A[M,K] * W[g][N,K]^T + bias[g][N] ----------------
// g = ((rowTile)/rows_per_group) % groups_mod.  act: 0 none, 1 relu, 2 softplus
__global__ __launch_bounds__(256) void gemm_kernel(
    const float* __restrict__ A, int lda,
    const float* __restrict__ W, int ldw,
    const float* __restrict__ bias,
    float* __restrict__ Cmat, int ldc,
    int M, int N, int K,
    int rows_per_group, int groups_mod, int act)
{
    __shared__ float As[16][64];
    __shared__ float Bs[16][64];
    int tx = threadIdx.x & 15, ty = threadIdx.x >> 4;
    int row0 = blockIdx.y * 64, col0 = blockIdx.x * 64;
    int g = (row0 / rows_per_group) % groups_mod;
    const float* Wg = W + (size_t)g * N * ldw;
    float acc[4][4] = {};
    for (int k0 = 0; k0 < K; k0 += 16) {
        for (int i = threadIdx.x; i < 1024; i += 256) {
            int mm = i >> 4, kk = i & 15;
            int r = row0 + mm, k = k0 + kk;
            As[kk][mm] = (r < M && k < K) ? A[(size_t)r * lda + k] : 0.f;
        }
        for (int i = threadIdx.x; i < 1024; i += 256) {
            int nn = i >> 4, kk = i & 15;
            int n = col0 + nn, k = k0 + kk;
            Bs[kk][nn] = (n < N && k < K) ? Wg[(size_t)n * ldw + k] : 0.f;
        }
        __syncthreads();
#pragma unroll
        for (int kk = 0; kk < 16; kk++) {
            float a0[4], b0[4];
            *(float4*)a0 = *(const float4*)&As[kk][ty * 4];
            *(float4*)b0 = *(const float4*)&Bs[kk][tx * 4];
#pragma unroll
            for (int i = 0; i < 4; i++)
#pragma unroll
                for (int j = 0; j < 4; j++)
                    acc[i][j] = fmaf(a0[i], b0[j], acc[i][j]);
        }
        __syncthreads();
    }
#pragma unroll
    for (int i = 0; i < 4; i++) {
        int r = row0 + ty * 4 + i;
        if (r >= M) continue;
#pragma unroll
        for (int j = 0; j < 4; j++) {
            int n = col0 + tx * 4 + j;
            if (n >= N) continue;
            float v = acc[i][j];
            if (bias) v += bias[(size_t)g * N + n];
            if (act == 1) v = fmaxf(v, 0.f);
            else if (act == 2) v = (v > 20.f) ? v : log1pf(__expf(v));
            Cmat[(size_t)r * ldc + n] = v;
        }
    }
}

// ---------------- depthwise 3x3 conv + SiLU, writes 4 scan directions ----------------
__global__ void conv_dw_kernel(const float* __restrict__ xz, const float* __restrict__ w,
                               const float* __restrict__ bias, float* __restrict__ xs)
{
    int bl = blockIdx.x;
    int b = bl / LL, l = bl % LL;
    int d = threadIdx.x;                       // 256
    int hh = l / W_, ww = l % W_;
    float acc = bias[d];
#pragma unroll
    for (int kh = 0; kh < 3; kh++) {
        int h2 = hh + kh - 1;
        if ((unsigned)h2 >= H_) continue;
#pragma unroll
        for (int kw = 0; kw < 3; kw++) {
            int w2 = ww + kw - 1;
            if ((unsigned)w2 >= W_) continue;
            acc = fmaf(w[d * 9 + kh * 3 + kw],
                       xz[((size_t)b * LL + h2 * W_ + w2) * 512 + d], acc);
        }
    }
    float sv = acc / (1.f + __expf(-acc));     // SiLU
    size_t base = (size_t)b * 4 * LL * DD + d;
    int l1 = ww * H_ + hh;
    xs[base + (size_t)l * DD]                      = sv;
    xs[base + (size_t)(LL + l1) * DD]              = sv;
    xs[base + (size_t)(2 * LL + (LL - 1 - l)) * DD]  = sv;
    xs[base + (size_t)(3 * LL + (LL - 1 - l1)) * DD] = sv;
}

// ---------------- selective scan: half-warp per (b,k,d), lane = n ----------------
__global__ __launch_bounds__(128) void scan_kernel(
    const float* __restrict__ dts, const float* __restrict__ xdbl,
    const float* __restrict__ xs, const float* __restrict__ A_log,
    const float* __restrict__ Ds, float* __restrict__ ys)
{
    int b = blockIdx.z, k = blockIdx.y;
    int tid = threadIdx.x, lane = tid & 31, wid = tid >> 5;
    int half = lane >> 4, n = lane & 15;
    int d = blockIdx.x * 8 + wid * 2 + half;
    float a  = -expf(A_log[((size_t)k * DD + d) * NN + n]);
    float Dv = Ds[k * DD + d];
    size_t row = (size_t)(b * 4 + k) * LL;
    const float* dt_p = dts  + row * DD + d;
    const float* x_p  = xs   + row * DD + d;
    const float* bc_p = xdbl + row * 40;
    float*       y_p  = ys   + row * DD + d;
    float h = 0.f;
#pragma unroll 4
    for (int l = 0; l < LL; l++) {
        float dt = dt_p[(size_t)l * DD];
        float xv = x_p[(size_t)l * DD];
        float Bn = bc_p[l * 40 + 8  + n];
        float Cn = bc_p[l * 40 + 24 + n];
        h = fmaf(h, __expf(dt * a), dt * xv * Bn);
        float y = h * Cn;
        y += __shfl_xor_sync(~0u, y, 8);
        y += __shfl_xor_sync(~0u, y, 4);
        y += __shfl_xor_sync(~0u, y, 2);
        y += __shfl_xor_sync(~0u, y, 1);
        if (n == 0) y_p[(size_t)l * DD] = fmaf(Dv, xv, y);
    }
}

// ---------------- combine 4 directions + out LayerNorm(D) + SiLU(z) gate ----------------
__global__ void combine_kernel(const float* __restrict__ ys, const float* __restrict__ xz,
                               const float* __restrict__ g, const float* __restrict__ bt,
                               float* __restrict__ yg)
{
    int bl = blockIdx.x;
    int b = bl / LL, l = bl % LL;
    int d = threadIdx.x;                  // 256
    int hh = l / W_, ww = l % W_;
    int l1 = ww * H_ + hh;
    size_t base = (size_t)b * 4 * LL * DD + d;
    float y = ys[base + (size_t)l * DD]
            + ys[base + (size_t)(LL + l1) * DD]
            + ys[base + (size_t)(2 * LL + (LL - 1 - l)) * DD]
            + ys[base + (size_t)(3 * LL + (LL - 1 - l1)) * DD];
    __shared__ float sh[8];
    __shared__ float stat;
    int lane = d & 31, wid = d >> 5;
    float t = y;
#pragma unroll
    for (int o = 16; o; o >>= 1) t += __shfl_xor_sync(~0u, t, o);
    if (lane == 0) sh[wid] = t;
    __syncthreads();
    if (d == 0) { float s = 0; for (int i = 0; i < 8; i++) s += sh[i]; stat = s * (1.f / DD); }
    __syncthreads();
    float mu = stat;
    float dy = y - mu;
    t = dy * dy;
#pragma unroll
    for (int o = 16; o; o >>= 1) t += __shfl_xor_sync(~0u, t, o);
    __syncthreads();
    if (lane == 0) sh[wid] = t;
    __syncthreads();
    if (d == 0) { float s = 0; for (int i = 0; i < 8; i++) s += sh[i]; stat = s * (1.f / DD); }
    __syncthreads();
    float inv = rsqrtf(stat + 1e-6f);
    float yn = dy * inv * g[d] + bt[d];
    float z  = xz[((size_t)b * LL + l) * 512 + 256 + d];
    float sig = 1.f / (1.f + __expf(-z));
    yg[((size_t)b * LL + l) * DD + d] = yn * z * sig;
}

// ---------------- self-attention (q=k=v), flash-style online softmax ----------------
__global__ __launch_bounds__(256) void attn_kernel(const float* __restrict__ xo,
                                                   float* __restrict__ o)
{
    const int qt = blockIdx.x, hh = blockIdx.y, b = blockIdx.z;
    __shared__ float Qs[32][33], Ks[32][33];
    int tid = threadIdx.x, lane = tid & 31, wid = tid >> 5;
    const float scale = 0.17677669529663687f;   // 1/sqrt(32)

    for (int i = tid; i < 1024; i += 256) {
        int r = i >> 5, c = i & 31;
        Qs[r][c] = xo[((size_t)b * LL + qt * 32 + r) * C_ + hh * 32 + c];
    }
    float O[4] = {0.f, 0.f, 0.f, 0.f};
    float mrow[4] = {-1e30f, -1e30f, -1e30f, -1e30f};
    float lrow[4] = {0.f, 0.f, 0.f, 0.f};
    __syncthreads();

    for (int kt = 0; kt < LL / 32; kt++) {
        for (int i = tid; i < 1024; i += 256) {
            int r = i >> 5, c = i & 31;
            Ks[r][c] = xo[((size_t)b * LL + kt * 32 + r) * C_ + hh * 32 + c];
        }
        __syncthreads();
#pragma unroll
        for (int r = 0; r < 4; r++) {
            int qi = wid * 4 + r;
            // scalar LDS: Qs[qi][dd] is a warp-broadcast, Ks[lane][dd] is
            // conflict-free (bank = (lane+dd) mod 32 with the 33-stride pad).
            float s = 0.f;
#pragma unroll
            for (int dd = 0; dd < 32; dd++)
                s = fmaf(Qs[qi][dd], Ks[lane][dd], s);
            s *= scale;
            float rm = s;
#pragma unroll
            for (int off = 16; off; off >>= 1) rm = fmaxf(rm, __shfl_xor_sync(~0u, rm, off));
            float nm = fmaxf(mrow[r], rm);
            float corr = __expf(mrow[r] - nm);
            float p = __expf(s - nm);
            float ps = p;
#pragma unroll
            for (int off = 16; off; off >>= 1) ps += __shfl_xor_sync(~0u, ps, off);
            lrow[r] = lrow[r] * corr + ps;
            float acc = O[r] * corr;
#pragma unroll
            for (int kk = 0; kk < 32; kk++) {
                float pk = __shfl_sync(~0u, p, kk);
                acc = fmaf(pk, Ks[kk][lane], acc);
            }
            O[r] = acc;
            mrow[r] = nm;
        }
        __syncthreads();
    }
#pragma unroll
    for (int r = 0; r < 4; r++) {
        int qi = wid * 4 + r;
        o[((size_t)b * LL + qt * 32 + qi) * C_ + hh * 32 + lane] = O[r] / lrow[r];
    }
}

// ---------------- ghost cheap branch: depthwise 3x3 on p (64ch) + relu ----------------
__global__ void ghost_dw_kernel(const float* __restrict__ p, const float* __restrict__ w,
                                const float* __restrict__ bias, float* __restrict__ ch)
{
    int bl = blockIdx.x;
    int b = bl / LL, l = bl % LL;
    int oc = threadIdx.x;                  // 64
    int hh = l / W_, ww = l % W_;
    float acc = bias[oc];
#pragma unroll
    for (int kh = 0; kh < 3; kh++) {
        int h2 = hh + kh - 1;
        if ((unsigned)h2 >= H_) continue;
#pragma unroll
        for (int kw = 0; kw < 3; kw++) {
            int w2 = ww + kw - 1;
            if ((unsigned)w2 >= W_) continue;
            acc = fmaf(w[oc * 9 + kh * 3 + kw],
                       p[((size_t)b * LL + h2 * W_ + w2) * 64 + oc], acc);
        }
    }
    ch[((size_t)b * LL + l) * 64 + oc] = fmaxf(acc, 0.f);
}

// ---------------- final: concat(p,ch) + residual, NCHW ----------------
__global__ void final_kernel(const float* __restrict__ p, const float* __restrict__ ch,
                             const float* __restrict__ x, float* __restrict__ out)
{
    int idx = blockIdx.x * 256 + threadIdx.x;
    if (idx >= B_ * C_ * LL) return;
    int hw = idx % LL;
    int c  = (idx / LL) % C_;
    int b  = idx / (C_ * LL);
    float v = (c < 64) ? p[((size_t)b * LL + hw) * 64 + c]
                       : ch[((size_t)b * LL + hw) * 64 + (c - 64)];
    out[idx] = v + x[idx];
}

// ---------------- launch ----------------
extern "C" void kernel_launch(void* const* d_in, const int* in_sizes, int n_in,
                              void* d_out, int out_size)
{
    const float* x          = (const float*)d_in[0];
    const float* norm_g     = (const float*)d_in[1];
    const float* norm_b     = (const float*)d_in[2];
    const float* in_proj_w  = (const float*)d_in[3];
    const float* in_proj_b  = (const float*)d_in[4];
    const float* conv_w     = (const float*)d_in[5];
    const float* conv_b     = (const float*)d_in[6];
    const float* x_proj_w   = (const float*)d_in[7];
    const float* dt_proj_w  = (const float*)d_in[8];
    const float* dt_proj_b  = (const float*)d_in[9];
    const float* A_log      = (const float*)d_in[10];
    const float* Ds         = (const float*)d_in[11];
    const float* out_norm_g = (const float*)d_in[12];
    const float* out_norm_b = (const float*)d_in[13];
    const float* out_proj_w = (const float*)d_in[14];
    const float* out_proj_b = (const float*)d_in[15];
    const float* g1_w       = (const float*)d_in[16];
    const float* g1_b       = (const float*)d_in[17];
    const float* g2_w       = (const float*)d_in[18];
    const float* g2_b       = (const float*)d_in[19];
    float* out = (float*)d_out;

    float* s = nullptr;
    cudaGetSymbolAddress((void**)&s, g_scratch);
    const int BIG = 1 << 30;

    // 1. LayerNorm (channels-last)
    ln_in_kernel<<<BL_ / 8, 256>>>(x, norm_g, norm_b, s + OFF_XN);
    // 2. in_proj: [4608,128] x [512,128]^T -> xz [4608,512]
    gemm_kernel<<<dim3(8, 72), 256>>>(s + OFF_XN, 128, in_proj_w, 128, in_proj_b,
                                      s + OFF_XZ, 512, BL_, 512, 128, BIG, 1, 0);
    // 3. depthwise conv + SiLU -> xs (4 directions)
    conv_dw_kernel<<<BL_, 256>>>(s + OFF_XZ, conv_w, conv_b, s + OFF_XS);
    // 4. x_proj (per-k weights): [18432,256] x [40,256]^T -> x_dbl [18432,40]
    gemm_kernel<<<dim3(1, 288), 256>>>(s + OFF_XS, 256, x_proj_w, 256, nullptr,
                                       s + OFF_XDBL, 40, BL_ * 4, 40, 256, LL, 4, 0);
    // 5. dt_proj + softplus: [18432,8(of 40)] x [256,8]^T -> dts [18432,256]
    gemm_kernel<<<dim3(4, 288), 256>>>(s + OFF_XDBL, 40, dt_proj_w, 8, dt_proj_b,
                                       s + OFF_DTS, 256, BL_ * 4, 256, 8, LL, 4, 2);
    // 6. selective scan
    scan_kernel<<<dim3(32, 4, 2), 128>>>(s + OFF_DTS, s + OFF_XDBL, s + OFF_XS,
                                         A_log, Ds, s + OFF_YS);
    // 7. combine + out LN + SiLU(z) gate
    combine_kernel<<<BL_, 256>>>(s + OFF_YS, s + OFF_XZ, out_norm_g, out_norm_b, s + OFF_YG);
    // 8. out_proj: [4608,256] x [128,256]^T -> xo [4608,128]
    gemm_kernel<<<dim3(2, 72), 256>>>(s + OFF_YG, 256, out_proj_w, 256, out_proj_b,
                                      s + OFF_XO, 128, BL_, 128, 256, BIG, 1, 0);
    // 9. self-attention
    attn_kernel<<<dim3(LL / 32, 4, B_), 256>>>(s + OFF_XO, s + OFF_AO);
    // 10. ghost primary 1x1 conv + relu: [4608,128] x [64,128]^T -> p
    gemm_kernel<<<dim3(1, 72), 256>>>(s + OFF_AO, 128, g1_w, 128, g1_b,
                                      s + OFF_P, 64, BL_, 64, 128, BIG, 1, 1);
    // 11. ghost cheap depthwise 3x3 + relu
    ghost_dw_kernel<<<BL_, 64>>>(s + OFF_P, g2_w, g2_b, s + OFF_CH);
    // 12. concat + residual
    final_kernel<<<(B_ * C_ * LL + 255) / 256, 256>>>(s + OFF_P, s + OFF_CH, x, out);
}

// round 3
// speedup vs baseline: 1.6089x; 1.6089x over previous
#include <cuda_runtime.h>
#include <cuda_bf16.h>
#include <math.h>
#include <stdint.h>

// ---------------- problem constants ----------------
#define B_   2
#define C_   128
#define H_   48
#define W_   48
#define LL   (H_*W_)      // 2304
#define DD   256
#define NN   16
#define RR   8
#define BL_  (B_*LL)      // 4608

// ---------------- scratch (device globals; no allocs allowed) ----------------
#define OFF_XN    ((size_t)0)          // [BL_,128]
#define OFF_XZ    ((size_t)589824)     // [BL_,512]
#define OFF_XS    ((size_t)2949120)    // [B,4,L,D]
#define OFF_XDBL  ((size_t)7667712)    // [B,4,L,40]
#define OFF_DTS   ((size_t)8404992)    // [B,4,L,D]
#define OFF_YS    ((size_t)13123584)   // [B,4,L,D]
#define OFF_YG    ((size_t)17842176)   // [BL_,D]
#define OFF_XO    ((size_t)19021824)   // [BL_,C]
#define OFF_AO    ((size_t)19611648)   // [BL_,C]
#define OFF_P     ((size_t)20201472)   // [BL_,64]
#define OFF_CH    ((size_t)20496384)   // [BL_,64]
#define SCRATCH_TOTAL 20791296

__device__ float g_scratch[SCRATCH_TOTAL];
__device__ __align__(16) __nv_bfloat16 g_xob[(size_t)B_ * 4 * LL * 32];  // [b][h][L][32]

// ---------------- LayerNorm over C=128 (channels-last output) ----------------
__global__ void ln_in_kernel(const float* __restrict__ x, const float* __restrict__ g,
                             const float* __restrict__ bt, float* __restrict__ xn)
{
    int row  = blockIdx.x * 8 + (threadIdx.x >> 5);
    int lane = threadIdx.x & 31;
    int b = row / LL, hw = row % LL;
    float v[4];
#pragma unroll
    for (int i = 0; i < 4; i++)
        v[i] = x[((size_t)b * C_ + (lane + 32*i)) * LL + hw];
    float s = v[0] + v[1] + v[2] + v[3];
#pragma unroll
    for (int o = 16; o; o >>= 1) s += __shfl_xor_sync(~0u, s, o);
    float mu = s * (1.f / C_);
    float q = 0.f;
#pragma unroll
    for (int i = 0; i < 4; i++) { float d = v[i] - mu; q += d * d; }
#pragma unroll
    for (int o = 16; o; o >>= 1) q += __shfl_xor_sync(~0u, q, o);
    float inv = rsqrtf(q * (1.f / C_) + 1e-6f);
#pragma unroll
    for (int i = 0; i < 4; i++) {
        int c = lane + 32*i;
        xn[(size_t)row * C_ + c] = (v[i] - mu) * inv * g[c] + bt[c];
    }
}

// ---------------- generic GEMM ----------------
__global__ __launch_bounds__(256) void gemm_kernel(
    const float* __restrict__ A, int lda,
    const float* __restrict__ W, int ldw,
    const float* __restrict__ bias,
    float* __restrict__ Cmat, int ldc,
    int M, int N, int K,
    int rows_per_group, int groups_mod, int act)
{
    __shared__ float As[16][64];
    __shared__ float Bs[16][64];
    int tx = threadIdx.x & 15, ty = threadIdx.x >> 4;
    int row0 = blockIdx.y * 64, col0 = blockIdx.x * 64;
    int g = (row0 / rows_per_group) % groups_mod;
    const float* Wg = W + (size_t)g * N * ldw;
    float acc[4][4] = {};
    for (int k0 = 0; k0 < K; k0 += 16) {
        for (int i = threadIdx.x; i < 1024; i += 256) {
            int mm = i >> 4, kk = i & 15;
            int r = row0 + mm, k = k0 + kk;
            As[kk][mm] = (r < M && k < K) ? A[(size_t)r * lda + k] : 0.f;
        }
        for (int i = threadIdx.x; i < 1024; i += 256) {
            int nn = i >> 4, kk = i & 15;
            int n = col0 + nn, k = k0 + kk;
            Bs[kk][nn] = (n < N && k < K) ? Wg[(size_t)n * ldw + k] : 0.f;
        }
        __syncthreads();
#pragma unroll
        for (int kk = 0; kk < 16; kk++) {
            float a0[4], b0[4];
            *(float4*)a0 = *(const float4*)&As[kk][ty * 4];
            *(float4*)b0 = *(const float4*)&Bs[kk][tx * 4];
#pragma unroll
            for (int i = 0; i < 4; i++)
#pragma unroll
                for (int j = 0; j < 4; j++)
                    acc[i][j] = fmaf(a0[i], b0[j], acc[i][j]);
        }
        __syncthreads();
    }
#pragma unroll
    for (int i = 0; i < 4; i++) {
        int r = row0 + ty * 4 + i;
        if (r >= M) continue;
#pragma unroll
        for (int j = 0; j < 4; j++) {
            int n = col0 + tx * 4 + j;
            if (n >= N) continue;
            float v = acc[i][j];
            if (bias) v += bias[(size_t)g * N + n];
            if (act == 1) v = fmaxf(v, 0.f);
            else if (act == 2) v = (v > 20.f) ? v : log1pf(__expf(v));
            Cmat[(size_t)r * ldc + n] = v;
        }
    }
}

// ---------------- specialized x_proj GEMM: [18432,256] x Wg[40,256]^T -> [18432,40] ----------------
__global__ __launch_bounds__(256) void xproj_kernel(const float* __restrict__ A,
                                                    const float* __restrict__ W,
                                                    float* __restrict__ out)
{
    __shared__ float As[128][36];
    __shared__ float Bs[32][45];
    int row0 = blockIdx.x * 128;
    int g = (row0 / LL) & 3;
    const float* Wg = W + (size_t)g * 40 * 256;
    int tx = threadIdx.x & 7;        // 8 -> cols tx + 8j, j<5
    int ty = threadIdx.x >> 3;       // 32 -> rows ty + 32i, i<4
    float acc[4][5] = {};
    for (int k0 = 0; k0 < 256; k0 += 32) {
        for (int i = threadIdx.x; i < 1024; i += 256) {
            int r = i >> 3, c4 = i & 7;
            float4 v = *(const float4*)&A[(size_t)(row0 + r) * 256 + k0 + c4 * 4];
            *(float4*)&As[r][c4 * 4] = v;
        }
        for (int i = threadIdx.x; i < 1280; i += 256) {
            int n = i >> 5, kk = i & 31;
            Bs[kk][n] = Wg[(size_t)n * 256 + k0 + kk];
        }
        __syncthreads();
#pragma unroll
        for (int kk = 0; kk < 32; kk++) {
            float av[4], bv[5];
#pragma unroll
            for (int i = 0; i < 4; i++) av[i] = As[ty + 32*i][kk];
#pragma unroll
            for (int j = 0; j < 5; j++) bv[j] = Bs[kk][tx + 8*j];
#pragma unroll
            for (int i = 0; i < 4; i++)
#pragma unroll
                for (int j = 0; j < 5; j++)
                    acc[i][j] = fmaf(av[i], bv[j], acc[i][j]);
        }
        __syncthreads();
    }
#pragma unroll
    for (int i = 0; i < 4; i++)
#pragma unroll
        for (int j = 0; j < 5; j++)
            out[(size_t)(row0 + ty + 32*i) * 40 + tx + 8*j] = acc[i][j];
}

// ---------------- depthwise 3x3 conv + SiLU, writes 4 scan directions ----------------
__global__ void conv_dw_kernel(const float* __restrict__ xz, const float* __restrict__ w,
                               const float* __restrict__ bias, float* __restrict__ xs)
{
    int bl = blockIdx.x;
    int b = bl / LL, l = bl % LL;
    int d = threadIdx.x;
    int hh = l / W_, ww = l % W_;
    float acc = bias[d];
#pragma unroll
    for (int kh = 0; kh < 3; kh++) {
        int h2 = hh + kh - 1;
        if ((unsigned)h2 >= H_) continue;
#pragma unroll
        for (int kw = 0; kw < 3; kw++) {
            int w2 = ww + kw - 1;
            if ((unsigned)w2 >= W_) continue;
            acc = fmaf(w[d * 9 + kh * 3 + kw],
                       xz[((size_t)b * LL + h2 * W_ + w2) * 512 + d], acc);
        }
    }
    float sv = acc / (1.f + __expf(-acc));
    size_t base = (size_t)b * 4 * LL * DD + d;
    int l1 = ww * H_ + hh;
    xs[base + (size_t)l * DD]                      = sv;
    xs[base + (size_t)(LL + l1) * DD]              = sv;
    xs[base + (size_t)(2 * LL + (LL - 1 - l)) * DD]  = sv;
    xs[base + (size_t)(3 * LL + (LL - 1 - l1)) * DD] = sv;
}

// ---------------- selective scan ----------------
__global__ __launch_bounds__(128) void scan_kernel(
    const float* __restrict__ dts, const float* __restrict__ xdbl,
    const float* __restrict__ xs, const float* __restrict__ A_log,
    const float* __restrict__ Ds, float* __restrict__ ys)
{
    int b = blockIdx.z, k = blockIdx.y;
    int tid = threadIdx.x, lane = tid & 31, wid = tid >> 5;
    int half = lane >> 4, n = lane & 15;
    int d = blockIdx.x * 8 + wid * 2 + half;
    float a  = -expf(A_log[((size_t)k * DD + d) * NN + n]);
    float Dv = Ds[k * DD + d];
    size_t row = (size_t)(b * 4 + k) * LL;
    const float* dt_p = dts  + row * DD + d;
    const float* x_p  = xs   + row * DD + d;
    const float* bc_p = xdbl + row * 40;
    float*       y_p  = ys   + row * DD + d;
    float h = 0.f;
#pragma unroll 4
    for (int l = 0; l < LL; l++) {
        float dt = dt_p[(size_t)l * DD];
        float xv = x_p[(size_t)l * DD];
        float Bn = bc_p[l * 40 + 8  + n];
        float Cn = bc_p[l * 40 + 24 + n];
        h = fmaf(h, __expf(dt * a), dt * xv * Bn);
        float y = h * Cn;
        y += __shfl_xor_sync(~0u, y, 8);
        y += __shfl_xor_sync(~0u, y, 4);
        y += __shfl_xor_sync(~0u, y, 2);
        y += __shfl_xor_sync(~0u, y, 1);
        if (n == 0) y_p[(size_t)l * DD] = fmaf(Dv, xv, y);
    }
}

// ---------------- combine + out LN + SiLU(z) gate ----------------
__global__ void combine_kernel(const float* __restrict__ ys, const float* __restrict__ xz,
                               const float* __restrict__ g, const float* __restrict__ bt,
                               float* __restrict__ yg)
{
    int bl = blockIdx.x;
    int b = bl / LL, l = bl % LL;
    int d = threadIdx.x;
    int hh = l / W_, ww = l % W_;
    int l1 = ww * H_ + hh;
    size_t base = (size_t)b * 4 * LL * DD + d;
    float y = ys[base + (size_t)l * DD]
            + ys[base + (size_t)(LL + l1) * DD]
            + ys[base + (size_t)(2 * LL + (LL - 1 - l)) * DD]
            + ys[base + (size_t)(3 * LL + (LL - 1 - l1)) * DD];
    __shared__ float sh[8];
    __shared__ float stat;
    int lane = d & 31, wid = d >> 5;
    float t = y;
#pragma unroll
    for (int o = 16; o; o >>= 1) t += __shfl_xor_sync(~0u, t, o);
    if (lane == 0) sh[wid] = t;
    __syncthreads();
    if (d == 0) { float s = 0; for (int i = 0; i < 8; i++) s += sh[i]; stat = s * (1.f / DD); }
    __syncthreads();
    float mu = stat;
    float dy = y - mu;
    t = dy * dy;
#pragma unroll
    for (int o = 16; o; o >>= 1) t += __shfl_xor_sync(~0u, t, o);
    __syncthreads();
    if (lane == 0) sh[wid] = t;
    __syncthreads();
    if (d == 0) { float s = 0; for (int i = 0; i < 8; i++) s += sh[i]; stat = s * (1.f / DD); }
    __syncthreads();
    float inv = rsqrtf(stat + 1e-6f);
    float yn = dy * inv * g[d] + bt[d];
    float z  = xz[((size_t)b * LL + l) * 512 + 256 + d];
    float sig = 1.f / (1.f + __expf(-z));
    yg[((size_t)b * LL + l) * DD + d] = yn * z * sig;
}

// ---------------- xo fp32 -> bf16 per-head layout [b][h][L][32] ----------------
__global__ void to_bf16_kernel(const float* __restrict__ xo, __nv_bfloat16* __restrict__ xob)
{
    int idx = blockIdx.x * 256 + threadIdx.x;
    if (idx >= BL_ * C_) return;
    int c = idx & 127;
    int l = (idx >> 7) % LL;
    int b = idx / (128 * LL);
    int h = c >> 5, d = c & 31;
    xob[(((size_t)(b * 4 + h)) * LL + l) * 32 + d] = __float2bfloat16(xo[idx]);
}

// ---------------- bf16 mma helpers ----------------
__device__ __forceinline__ void mma16816(float c[4], uint32_t a0, uint32_t a1,
                                         uint32_t a2, uint32_t a3,
                                         uint32_t b0, uint32_t b1)
{
    asm volatile(
        "mma.sync.aligned.m16n8k16.row.col.f32.bf16.bf16.f32 "
        "{%0,%1,%2,%3}, {%4,%5,%6,%7}, {%8,%9}, {%0,%1,%2,%3};\n"
        : "+f"(c[0]), "+f"(c[1]), "+f"(c[2]), "+f"(c[3])
        : "r"(a0), "r"(a1), "r"(a2), "r"(a3), "r"(b0), "r"(b1));
}

__device__ __forceinline__ uint32_t f2bf2(float lo, float hi)
{
    __nv_bfloat162 h2 = __floats2bfloat162_rn(lo, hi);
    return *(uint32_t*)&h2;
}

// ---------------- flash attention, bf16 tensor cores ----------------
// grid (36, 4 heads, B), block 128 (4 warps x 16 q rows)
__global__ __launch_bounds__(128) void attn_mma_kernel(const __nv_bfloat16* __restrict__ xob,
                                                       float* __restrict__ o)
{
    const int qt = blockIdx.x, h = blockIdx.y, b = blockIdx.z;
    const __nv_bfloat16* base = xob + ((size_t)(b * 4 + h)) * LL * 32;

    __shared__ __align__(16) __nv_bfloat16 Qs[64][40];
    __shared__ __align__(16) __nv_bfloat16 Ks[64][40];

    int tid = threadIdx.x, lane = tid & 31, w = tid >> 5;
    int g = lane >> 2, t = lane & 3;
    const float scale = 0.17677669529663687f;   // 1/sqrt(32)

    // load Q tile (64 x 32)
    {
        int r = tid >> 1, half = tid & 1;
        const uint4* src = (const uint4*)(base + ((size_t)(qt * 64 + r)) * 32 + half * 16);
        uint4 v0 = src[0], v1 = src[1];
        *(uint4*)&Qs[r][half * 16] = v0;
        (void)v1; // row is exactly 32 bf16 = 2 uint4 per half? no: half covers 16 bf16 = 32B = 2 uint4
        *(uint4*)&Qs[r][half * 16 + 8] = v1;
    }
    __syncthreads();

    // Q fragments (persistent)
    uint32_t qa[2][4];
    int qr = w * 16;
#pragma unroll
    for (int k2 = 0; k2 < 2; k2++) {
        qa[k2][0] = *(const uint32_t*)&Qs[qr + g    ][16 * k2 + 2 * t];
        qa[k2][1] = *(const uint32_t*)&Qs[qr + g + 8][16 * k2 + 2 * t];
        qa[k2][2] = *(const uint32_t*)&Qs[qr + g    ][16 * k2 + 2 * t + 8];
        qa[k2][3] = *(const uint32_t*)&Qs[qr + g + 8][16 * k2 + 2 * t + 8];
    }

    float m0 = -1e30f, m1 = -1e30f, l0 = 0.f, l1 = 0.f;
    float O[4][4] = {};

    for (int kt = 0; kt < LL / 64; kt++) {
        __syncthreads();
        {
            int r = tid >> 1, half = tid & 1;
            const uint4* src = (const uint4*)(base + ((size_t)(kt * 64 + r)) * 32 + half * 16);
            uint4 v0 = src[0], v1 = src[1];
            *(uint4*)&Ks[r][half * 16] = v0;
            *(uint4*)&Ks[r][half * 16 + 8] = v1;
        }
        __syncthreads();

        // S = Q K^T  (16 x 64 per warp)
        float s[8][4];
#pragma unroll
        for (int ns = 0; ns < 8; ns++) {
            s[ns][0] = s[ns][1] = s[ns][2] = s[ns][3] = 0.f;
            uint32_t b0 = *(const uint32_t*)&Ks[8 * ns + g][2 * t];
            uint32_t b1 = *(const uint32_t*)&Ks[8 * ns + g][2 * t + 8];
            mma16816(s[ns], qa[0][0], qa[0][1], qa[0][2], qa[0][3], b0, b1);
            uint32_t b2 = *(const uint32_t*)&Ks[8 * ns + g][16 + 2 * t];
            uint32_t b3 = *(const uint32_t*)&Ks[8 * ns + g][16 + 2 * t + 8];
            mma16816(s[ns], qa[1][0], qa[1][1], qa[1][2], qa[1][3], b2, b3);
        }
        // scale + row max
        float rm0 = -1e30f, rm1 = -1e30f;
#pragma unroll
        for (int ns = 0; ns < 8; ns++) {
            s[ns][0] *= scale; s[ns][1] *= scale; s[ns][2] *= scale; s[ns][3] *= scale;
            rm0 = fmaxf(rm0, fmaxf(s[ns][0], s[ns][1]));
            rm1 = fmaxf(rm1, fmaxf(s[ns][2], s[ns][3]));
        }
        rm0 = fmaxf(rm0, __shfl_xor_sync(~0u, rm0, 1));
        rm0 = fmaxf(rm0, __shfl_xor_sync(~0u, rm0, 2));
        rm1 = fmaxf(rm1, __shfl_xor_sync(~0u, rm1, 1));
        rm1 = fmaxf(rm1, __shfl_xor_sync(~0u, rm1, 2));
        float nm0 = fmaxf(m0, rm0), nm1 = fmaxf(m1, rm1);
        float corr0 = __expf(m0 - nm0), corr1 = __expf(m1 - nm1);
        m0 = nm0; m1 = nm1;
        float ps0 = 0.f, ps1 = 0.f;
#pragma unroll
        for (int ns = 0; ns < 8; ns++) {
            s[ns][0] = __expf(s[ns][0] - nm0);
            s[ns][1] = __expf(s[ns][1] - nm0);
            s[ns][2] = __expf(s[ns][2] - nm1);
            s[ns][3] = __expf(s[ns][3] - nm1);
            ps0 += s[ns][0] + s[ns][1];
            ps1 += s[ns][2] + s[ns][3];
        }
        ps0 += __shfl_xor_sync(~0u, ps0, 1); ps0 += __shfl_xor_sync(~0u, ps0, 2);
        ps1 += __shfl_xor_sync(~0u, ps1, 1); ps1 += __shfl_xor_sync(~0u, ps1, 2);
        l0 = l0 * corr0 + ps0;
        l1 = l1 * corr1 + ps1;
#pragma unroll
        for (int ns2 = 0; ns2 < 4; ns2++) {
            O[ns2][0] *= corr0; O[ns2][1] *= corr0;
            O[ns2][2] *= corr1; O[ns2][3] *= corr1;
        }
        // pack P -> bf16 A fragments (C->A register identity)
        uint32_t pa[4][4];
#pragma unroll
        for (int kk = 0; kk < 4; kk++) {
            pa[kk][0] = f2bf2(s[2*kk][0],   s[2*kk][1]);
            pa[kk][1] = f2bf2(s[2*kk][2],   s[2*kk][3]);
            pa[kk][2] = f2bf2(s[2*kk+1][0], s[2*kk+1][1]);
            pa[kk][3] = f2bf2(s[2*kk+1][2], s[2*kk+1][3]);
        }
        // O += P V   (V = K tile, row-major [key][dh])
#pragma unroll
        for (int ns2 = 0; ns2 < 4; ns2++) {
#pragma unroll
            for (int kk = 0; kk < 4; kk++) {
                int kb = 16 * kk + 2 * t;
                int nc = 8 * ns2 + g;
                uint32_t vb0 = ((uint32_t)*(const unsigned short*)&Ks[kb + 1][nc] << 16)
                             |  (uint32_t)*(const unsigned short*)&Ks[kb    ][nc];
                uint32_t vb1 = ((uint32_t)*(const unsigned short*)&Ks[kb + 9][nc] << 16)
                             |  (uint32_t)*(const unsigned short*)&Ks[kb + 8][nc];
                mma16816(O[ns2], pa[kk][0], pa[kk][1], pa[kk][2], pa[kk][3], vb0, vb1);
            }
        }
    }

    float inv0 = 1.f / l0, inv1 = 1.f / l1;
    int row0 = b * LL + qt * 64 + qr + g;
#pragma unroll
    for (int ns2 = 0; ns2 < 4; ns2++) {
        int col = h * 32 + 8 * ns2 + 2 * t;
        float2 v0 = make_float2(O[ns2][0] * inv0, O[ns2][1] * inv0);
        float2 v1 = make_float2(O[ns2][2] * inv1, O[ns2][3] * inv1);
        *(float2*)&o[(size_t)row0 * C_ + col]       = v0;
        *(float2*)&o[(size_t)(row0 + 8) * C_ + col] = v1;
    }
}

// ---------------- ghost cheap branch ----------------
__global__ void ghost_dw_kernel(const float* __restrict__ p, const float* __restrict__ w,
                                const float* __restrict__ bias, float* __restrict__ ch)
{
    int bl = blockIdx.x;
    int b = bl / LL, l = bl % LL;
    int oc = threadIdx.x;
    int hh = l / W_, ww = l % W_;
    float acc = bias[oc];
#pragma unroll
    for (int kh = 0; kh < 3; kh++) {
        int h2 = hh + kh - 1;
        if ((unsigned)h2 >= H_) continue;
#pragma unroll
        for (int kw = 0; kw < 3; kw++) {
            int w2 = ww + kw - 1;
            if ((unsigned)w2 >= W_) continue;
            acc = fmaf(w[oc * 9 + kh * 3 + kw],
                       p[((size_t)b * LL + h2 * W_ + w2) * 64 + oc], acc);
        }
    }
    ch[((size_t)b * LL + l) * 64 + oc] = fmaxf(acc, 0.f);
}

// ---------------- final: concat + residual ----------------
__global__ void final_kernel(const float* __restrict__ p, const float* __restrict__ ch,
                             const float* __restrict__ x, float* __restrict__ out)
{
    int idx = blockIdx.x * 256 + threadIdx.x;
    if (idx >= B_ * C_ * LL) return;
    int hw = idx % LL;
    int c  = (idx / LL) % C_;
    int b  = idx / (C_ * LL);
    float v = (c < 64) ? p[((size_t)b * LL + hw) * 64 + c]
                       : ch[((size_t)b * LL + hw) * 64 + (c - 64)];
    out[idx] = v + x[idx];
}

// ---------------- launch ----------------
extern "C" void kernel_launch(void* const* d_in, const int* in_sizes, int n_in,
                              void* d_out, int out_size)
{
    const float* x          = (const float*)d_in[0];
    const float* norm_g     = (const float*)d_in[1];
    const float* norm_b     = (const float*)d_in[2];
    const float* in_proj_w  = (const float*)d_in[3];
    const float* in_proj_b  = (const float*)d_in[4];
    const float* conv_w     = (const float*)d_in[5];
    const float* conv_b     = (const float*)d_in[6];
    const float* x_proj_w   = (const float*)d_in[7];
    const float* dt_proj_w  = (const float*)d_in[8];
    const float* dt_proj_b  = (const float*)d_in[9];
    const float* A_log      = (const float*)d_in[10];
    const float* Ds         = (const float*)d_in[11];
    const float* out_norm_g = (const float*)d_in[12];
    const float* out_norm_b = (const float*)d_in[13];
    const float* out_proj_w = (const float*)d_in[14];
    const float* out_proj_b = (const float*)d_in[15];
    const float* g1_w       = (const float*)d_in[16];
    const float* g1_b       = (const float*)d_in[17];
    const float* g2_w       = (const float*)d_in[18];
    const float* g2_b       = (const float*)d_in[19];
    float* out = (float*)d_out;

    float* s = nullptr;
    cudaGetSymbolAddress((void**)&s, g_scratch);
    __nv_bfloat16* xob = nullptr;
    cudaGetSymbolAddress((void**)&xob, g_xob);
    const int BIG = 1 << 30;

    ln_in_kernel<<<BL_ / 8, 256>>>(x, norm_g, norm_b, s + OFF_XN);
    gemm_kernel<<<dim3(8, 72), 256>>>(s + OFF_XN, 128, in_proj_w, 128, in_proj_b,
                                      s + OFF_XZ, 512, BL_, 512, 128, BIG, 1, 0);
    conv_dw_kernel<<<BL_, 256>>>(s + OFF_XZ, conv_w, conv_b, s + OFF_XS);
    xproj_kernel<<<144, 256>>>(s + OFF_XS, x_proj_w, s + OFF_XDBL);
    gemm_kernel<<<dim3(4, 288), 256>>>(s + OFF_XDBL, 40, dt_proj_w, 8, dt_proj_b,
                                       s + OFF_DTS, 256, BL_ * 4, 256, 8, LL, 4, 2);
    scan_kernel<<<dim3(32, 4, 2), 128>>>(s + OFF_DTS, s + OFF_XDBL, s + OFF_XS,
                                         A_log, Ds, s + OFF_YS);
    combine_kernel<<<BL_, 256>>>(s + OFF_YS, s + OFF_XZ, out_norm_g, out_norm_b, s + OFF_YG);
    gemm_kernel<<<dim3(2, 72), 256>>>(s + OFF_YG, 256, out_proj_w, 256, out_proj_b,
                                      s + OFF_XO, 128, BL_, 128, 256, BIG, 1, 0);
    to_bf16_kernel<<<(BL_ * C_ + 255) / 256, 256>>>(s + OFF_XO, xob);
    attn_mma_kernel<<<dim3(LL / 64, 4, B_), 128>>>(xob, s + OFF_AO);
    gemm_kernel<<<dim3(1, 72), 256>>>(s + OFF_AO, 128, g1_w, 128, g1_b,
                                      s + OFF_P, 64, BL_, 64, 128, BIG, 1, 1);
    ghost_dw_kernel<<<BL_, 64>>>(s + OFF_P, g2_w, g2_b, s + OFF_CH);
    final_kernel<<<(B_ * C_ * LL + 255) / 256, 256>>>(s + OFF_P, s + OFF_CH, x, out);
}